// round 9
// baseline (speedup 1.0000x reference)
#include <cuda_runtime.h>
#include <math.h>

#define B_ROWS 64
#define N_PTS 1024
#define HID 256
#define KMAX 64
#define PROM_MIN 0.1f
#define LEVELS 10

__device__ __forceinline__ unsigned ordf(float f) {
    unsigned u = __float_as_uint(f);
    return (u & 0x80000000u) ? ~u : (u | 0x80000000u);
}

struct alignas(16) Shm {
    float xs[N_PTS];
    float2 tab[LEVELS][N_PTS];  // .x = max, .y = min over [j, j+2^k)
    float part[4][HID];
    float w1r[HID];
    float red[8];
    float wmin[8], wmax[8];
    unsigned long long wtop[8 * KMAX];
    unsigned long long blk[KMAX];
    int   cnt;
    int   nz;
    float h1[HID];
};

// one extraction round via 2 REDUX ops. key = (ordscore<<32) | ~index.
__device__ __forceinline__ unsigned long long warp_extract_max(unsigned long long b)
{
    unsigned bs   = (unsigned)(b >> 32);
    unsigned bidx = ~(unsigned)b;
    unsigned wmax = __reduce_max_sync(0xffffffffu, bs);
    unsigned cand = (bs == wmax) ? bidx : 0xffffffffu;
    unsigned widx = __reduce_min_sync(0xffffffffu, cand);
    return ((unsigned long long)wmax << 32) | (unsigned)(~widx);
}

// ---------------------------------------------------------------------------
// select core. Requires: s->xs and s->tab[0] filled, threads synced.
// ---------------------------------------------------------------------------
__device__ __forceinline__ void select_core(Shm* s, float* out_idx_row, int K)
{
    int tid  = threadIdx.x;
    int w    = tid >> 5;
    int lane = tid & 31;

    if (tid == 0) s->cnt = 0;

    // sparse table levels 1..9
    #pragma unroll
    for (int k = 1; k < LEVELS; k++) {
        int half = 1 << (k - 1);
        __syncthreads();
        #pragma unroll
        for (int sgi = 0; sgi < 4; sgi++) {
            int j  = tid + 256 * sgi;
            int j2 = j + half; if (j2 > N_PTS - 1) j2 = N_PTS - 1;
            float2 a = s->tab[k - 1][j];
            float2 b = s->tab[k - 1][j2];
            s->tab[k][j] = make_float2(fmaxf(a.x, b.x), fminf(a.y, b.y));
        }
    }
    __syncthreads();

    float xv[4], promv[4];
    bool  validv[4];
    int   wcnt = 0;

    #pragma unroll
    for (int sgi = 0; sgi < 4; sgi++) {
        int i = tid + 256 * sgi;
        float xi = s->xs[i];
        xv[sgi] = xi;

        // cheap 2-neighbor peak test first; prominence ONLY for peaks
        bool peak = (i > 0) && (i < N_PTS - 1) &&
                    (xi > s->xs[i - 1]) && (xi > s->xs[i + 1]);

        float prom = -INFINITY;
        if (peak) {
            // lb: previous strictly-greater via binary lifting
            int pos = i;
            #pragma unroll
            for (int k = LEVELS - 1; k >= 0; k--) {
                int cand = pos - (1 << k);
                if (cand >= 0 && s->tab[k][cand].x <= xi) pos = cand;
            }
            int lb = pos - 1; if (lb < 0) lb = 0;

            // rb: next strictly-greater
            int pos2 = i + 1;
            #pragma unroll
            for (int k = LEVELS - 1; k >= 0; k--) {
                if (pos2 + (1 << k) <= N_PTS && s->tab[k][pos2].x <= xi) pos2 += (1 << k);
            }
            int rb = pos2; if (rb > N_PTS - 1) rb = N_PTS - 1;

            // RMQ mins over [lb,i] and [i,rb]
            int lenL = i - lb + 1;
            int kL = 31 - __clz(lenL); if (kL > LEVELS - 1) kL = LEVELS - 1;
            float lm = fminf(s->tab[kL][lb].y, s->tab[kL][i - (1 << kL) + 1].y);

            int lenR = rb - i + 1;
            int kR = 31 - __clz(lenR); if (kR > LEVELS - 1) kR = LEVELS - 1;
            float rm = fminf(s->tab[kR][i].y, s->tab[kR][rb - (1 << kR) + 1].y);

            prom = xi - fmaxf(lm, rm);
        }

        bool valid = peak && (prom >= PROM_MIN);
        promv[sgi]  = prom;
        validv[sgi] = valid;

        unsigned bal = __ballot_sync(0xffffffffu, valid);
        if (lane == 0) wcnt += __popc(bal);
    }
    if (lane == 0 && wcnt) atomicAdd(&s->cnt, wcnt);
    __syncthreads();

    bool useA = (s->cnt >= K);
    unsigned long long key[4];
    #pragma unroll
    for (int sgi = 0; sgi < 4; sgi++) {
        int i = tid + 256 * sgi;
        float sc = useA ? (validv[sgi] ? promv[sgi] : -INFINITY) : xv[sgi];
        key[sgi] = ((unsigned long long)ordf(sc) << 32) | (unsigned)(~(unsigned)i);
    }

    if (K <= 32) {
        // ---- phase 1: per-warp top-K via REDUX rounds ----
        for (int it = 0; it < K; it++) {
            unsigned long long b = key[0];
            if (key[1] > b) b = key[1];
            if (key[2] > b) b = key[2];
            if (key[3] > b) b = key[3];
            unsigned long long win = warp_extract_max(b);
            if (lane == 0) s->wtop[w * K + it] = win;
            #pragma unroll
            for (int sgi = 0; sgi < 4; sgi++)
                if (key[sgi] == win) key[sgi] = 0ULL;
        }
        __syncthreads();

        // ---- phase 2: warp 0 selects global top-K from 8*K survivors ----
        if (w == 0) {
            unsigned long long pk[8];
            int total = 8 * K;
            #pragma unroll
            for (int m = 0; m < 8; m++) {
                int idx = lane + 32 * m;
                pk[m] = (idx < total) ? s->wtop[idx] : 0ULL;
            }
            for (int it = 0; it < K; it++) {
                unsigned long long b = pk[0];
                #pragma unroll
                for (int m = 1; m < 8; m++)
                    if (pk[m] > b) b = pk[m];
                unsigned long long win = warp_extract_max(b);
                if (lane == 0) s->blk[it] = win;
                #pragma unroll
                for (int m = 0; m < 8; m++)
                    if (pk[m] == win) pk[m] = 0ULL;
            }
            int idx = (lane < K) ? (int)(~(unsigned)(s->blk[lane] & 0xffffffffULL))
                                 : 0x7fffffff;
            int rank = 0;
            #pragma unroll
            for (int m = 0; m < 32; m++) {
                int v = __shfl_sync(0xffffffffu, idx, m);
                rank += (v < idx) ? 1 : 0;
            }
            if (lane < K) out_idx_row[rank] = (float)idx;
        }
    } else {
        // generic cold path (K > 32)
        for (int it = tid; it < KMAX; it += 256) s->blk[it] = 0ULL;
        __syncthreads();
        for (int it = 0; it < K; it++) {
            unsigned long long b = key[0];
            if (key[1] > b) b = key[1];
            if (key[2] > b) b = key[2];
            if (key[3] > b) b = key[3];
            unsigned long long win = warp_extract_max(b);
            if (lane == 0) atomicMax(&s->blk[it], win);
            __syncthreads();
            unsigned widx = ~(unsigned)(s->blk[it] & 0xffffffffULL);
            #pragma unroll
            for (int sgi = 0; sgi < 4; sgi++)
                if ((unsigned)(tid + 256 * sgi) == widx) key[sgi] = 0ULL;
        }
        if (tid == 0) {
            int sel[KMAX];
            for (int it = 0; it < K; it++)
                sel[it] = (int)(~(unsigned)(s->blk[it] & 0xffffffffULL));
            for (int a = 1; a < K; a++) {
                int v = sel[a], b = a - 1;
                while (b >= 0 && sel[b] > v) { sel[b + 1] = sel[b]; b--; }
                sel[b + 1] = v;
            }
            for (int a = 0; a < K; a++) out_idx_row[a] = (float)sel[a];
        }
    }
}

// ---------------------------------------------------------------------------
// Single fused kernel: 64 blocks x 256 threads, one row per block.
// ---------------------------------------------------------------------------
__global__ void __launch_bounds__(256, 1)
fused_all(const float* __restrict__ tp,
          const float* __restrict__ W1, const float* __restrict__ b1,
          const float* __restrict__ W2, const float* __restrict__ b2,
          const float* __restrict__ W3, const float* __restrict__ b3,
          float* __restrict__ out_density,
          float* __restrict__ out_idx, int K)
{
    extern __shared__ char raw[];
    Shm* s = reinterpret_cast<Shm*>(raw);

    int row  = blockIdx.x;
    int tid  = threadIdx.x;
    int w    = tid >> 5;
    int lane = tid & 31;
    const float* x = tp + row * N_PTS;

    float tv[4];
    float mn = INFINITY, mx = -INFINITY;
    #pragma unroll
    for (int sgi = 0; sgi < 4; sgi++) {
        float v = x[tid + 256 * sgi];
        tv[sgi] = v;
        mn = fminf(mn, v);
        mx = fmaxf(mx, v);
    }
    s->w1r[tid] = fmaxf(W1[tid], 0.0f);
    if (tid == 0) s->nz = 0;

    #pragma unroll
    for (int o = 16; o; o >>= 1) {
        mn = fminf(mn, __shfl_xor_sync(0xffffffffu, mn, o));
        mx = fmaxf(mx, __shfl_xor_sync(0xffffffffu, mx, o));
    }
    if (lane == 0) { s->wmin[w] = mn; s->wmax[w] = mx; }
    if (b1[tid] != 0.0f || b2[tid] != 0.0f) atomicAdd(&s->nz, 1);
    __syncthreads();

    float tmin = s->wmin[0], tmaxv = s->wmax[0];
    #pragma unroll
    for (int i = 1; i < 8; i++) {
        tmin  = fminf(tmin,  s->wmin[i]);
        tmaxv = fmaxf(tmaxv, s->wmax[i]);
    }
    float inv = 1.0f / fmaxf(tmaxv - tmin, 1e-6f);

    // c-compute: thread owns 4 consecutive j (float4) and 64-wide k strip
    {
        int p  = tid >> 6;
        int jj = tid & 63;
        const float4* W2v = reinterpret_cast<const float4*>(W2);
        float4 u4 = make_float4(0.f, 0.f, 0.f, 0.f);
        int k0 = p << 6;
        #pragma unroll 8
        for (int k = k0; k < k0 + 64; k++) {
            float wv = s->w1r[k];
            float4 r = W2v[k * (HID / 4) + jj];
            u4.x = fmaf(wv, r.x, u4.x);
            u4.y = fmaf(wv, r.y, u4.y);
            u4.z = fmaf(wv, r.z, u4.z);
            u4.w = fmaf(wv, r.w, u4.w);
        }
        reinterpret_cast<float4*>(s->part[p])[jj] = u4;
    }
    __syncthreads();
    {
        float U = s->part[0][tid] + s->part[1][tid]
                + s->part[2][tid] + s->part[3][tid];
        float rj = fmaxf(U, 0.0f) * W3[tid];
        #pragma unroll
        for (int o = 16; o; o >>= 1)
            rj += __shfl_xor_sync(0xffffffffu, rj, o);
        if (lane == 0) s->red[w] = rj;
    }
    __syncthreads();
    float c = s->red[0] + s->red[1] + s->red[2] + s->red[3]
            + s->red[4] + s->red[5] + s->red[6] + s->red[7];
    bool fast = (s->nz == 0);
    float b3v = b3[0];

    if (fast) {
        #pragma unroll
        for (int sgi = 0; sgi < 4; sgi++) {
            int i = tid + 256 * sgi;
            float t = (tv[sgi] - tmin) * inv;
            float v = fmaf(c, t, b3v);
            float d = fmaxf(v, 0.0f) + log1pf(expf(-fabsf(v)));
            s->xs[i] = d;
            s->tab[0][i] = make_float2(d, d);
            out_density[row * N_PTS + i] = d;
        }
    } else {
        #pragma unroll
        for (int sgi = 0; sgi < 4; sgi++) {
            int i = tid + 256 * sgi;
            s->xs[i] = (tv[sgi] - tmin) * inv;
        }
        __syncthreads();
        for (int e = 0; e < N_PTS; e++) {
            float t = s->xs[e];
            s->h1[tid] = fmaxf(fmaf(t, W1[tid], b1[tid]), 0.0f);
            __syncthreads();
            float acc = b2[tid];
            #pragma unroll 8
            for (int k = 0; k < HID; k++)
                acc = fmaf(s->h1[k], W2[k * HID + tid], acc);
            float vj = fmaxf(acc, 0.0f) * W3[tid];
            #pragma unroll
            for (int o = 16; o; o >>= 1)
                vj += __shfl_xor_sync(0xffffffffu, vj, o);
            if (lane == 0) s->red[w] = vj;
            __syncthreads();
            if (tid == 0) {
                float sum = s->red[0] + s->red[1] + s->red[2] + s->red[3]
                          + s->red[4] + s->red[5] + s->red[6] + s->red[7] + b3v;
                float d = fmaxf(sum, 0.0f) + log1pf(expf(-fabsf(sum)));
                out_density[row * N_PTS + e] = d;
                s->h1[0] = d;
            }
            __syncthreads();
            float d = s->h1[0];
            if (tid == 0) {
                s->xs[e] = d;
                s->tab[0][e] = make_float2(d, d);
            }
            __syncthreads();
        }
    }
    __syncthreads();

    select_core(s, out_idx + row * K, K);
}

// ---------------------------------------------------------------------------
extern "C" void kernel_launch(void* const* d_in, const int* in_sizes, int n_in,
                              void* d_out, int out_size)
{
    const float* time_points = (const float*)d_in[0];
    const float* W1 = (const float*)d_in[2];
    const float* b1 = (const float*)d_in[3];
    const float* W2 = (const float*)d_in[4];
    const float* b2 = (const float*)d_in[5];
    const float* W3 = (const float*)d_in[6];
    const float* b3 = (const float*)d_in[7];

    float* out = (float*)d_out;
    float* out_density = out;
    float* out_indices = out + B_ROWS * N_PTS;

    int K = (out_size - B_ROWS * N_PTS) / B_ROWS;
    if (K < 1) K = 16;
    if (K > KMAX) K = KMAX;

    int smem = (int)sizeof(Shm);
    cudaFuncSetAttribute(fused_all, cudaFuncAttributeMaxDynamicSharedMemorySize, smem);

    fused_all<<<B_ROWS, 256, smem>>>(time_points, W1, b1, W2, b2, W3, b3,
                                     out_density, out_indices, K);
}

// round 10
// speedup vs baseline: 1.1509x; 1.1509x over previous
#include <cuda_runtime.h>
#include <math.h>

#define B_ROWS 64
#define N_PTS 1024
#define HID 256
#define KMAX 64
#define PROM_MIN 0.1f
#define LEVELS 10
#define NTHR 512
#define NE 2            // elements per thread
#define NW 16           // warps per block

__device__ __forceinline__ unsigned ordf(float f) {
    unsigned u = __float_as_uint(f);
    return (u & 0x80000000u) ? ~u : (u | 0x80000000u);
}

struct alignas(16) Shm {
    float xs[N_PTS];
    float tabmax[LEVELS][N_PTS];   // max over [j, j+2^k)
    float tabmin[LEVELS][N_PTS];   // min over [j, j+2^k)
    float part[8][HID];
    float w1r[HID];
    float red[NW];
    float wmin[NW], wmax[NW];
    unsigned long long wtop[NW * 32];
    unsigned long long blk[KMAX];
    int   cnt;
    int   nz;
    float h1[HID];
};

// one extraction round via 2 REDUX ops. key = (ordscore<<32) | ~index.
__device__ __forceinline__ unsigned long long warp_extract_max(unsigned long long b)
{
    unsigned bs   = (unsigned)(b >> 32);
    unsigned bidx = ~(unsigned)b;
    unsigned wmax = __reduce_max_sync(0xffffffffu, bs);
    unsigned cand = (bs == wmax) ? bidx : 0xffffffffu;
    unsigned widx = __reduce_min_sync(0xffffffffu, cand);
    return ((unsigned long long)wmax << 32) | (unsigned)(~widx);
}

// ---------------------------------------------------------------------------
// select core. Requires: s->xs, s->tabmax[0], s->tabmin[0] filled, synced.
// ---------------------------------------------------------------------------
__device__ __forceinline__ void select_core(Shm* s, float* out_idx_row, int K)
{
    int tid  = threadIdx.x;
    int w    = tid >> 5;
    int lane = tid & 31;

    if (tid == 0) s->cnt = 0;

    // sparse table levels 1..9
    #pragma unroll
    for (int k = 1; k < LEVELS; k++) {
        int half = 1 << (k - 1);
        __syncthreads();
        #pragma unroll
        for (int sgi = 0; sgi < NE; sgi++) {
            int j  = tid + NTHR * sgi;
            int j2 = j + half; if (j2 > N_PTS - 1) j2 = N_PTS - 1;
            s->tabmax[k][j] = fmaxf(s->tabmax[k - 1][j], s->tabmax[k - 1][j2]);
            s->tabmin[k][j] = fminf(s->tabmin[k - 1][j], s->tabmin[k - 1][j2]);
        }
    }
    __syncthreads();

    float xv[NE], promv[NE];
    bool  validv[NE];
    int   wcnt = 0;

    #pragma unroll
    for (int sgi = 0; sgi < NE; sgi++) {
        int i = tid + NTHR * sgi;
        float xi = s->xs[i];
        xv[sgi] = xi;

        // lb: previous strictly-greater via binary lifting
        int pos = i;
        #pragma unroll
        for (int k = LEVELS - 1; k >= 0; k--) {
            int cand = pos - (1 << k);
            if (cand >= 0 && s->tabmax[k][cand] <= xi) pos = cand;
        }
        int lb = pos - 1; if (lb < 0) lb = 0;

        // rb: next strictly-greater
        int pos2 = i + 1;
        #pragma unroll
        for (int k = LEVELS - 1; k >= 0; k--) {
            if (pos2 + (1 << k) <= N_PTS && s->tabmax[k][pos2] <= xi) pos2 += (1 << k);
        }
        int rb = pos2; if (rb > N_PTS - 1) rb = N_PTS - 1;

        // RMQ mins over [lb,i] and [i,rb]
        int lenL = i - lb + 1;
        int kL = 31 - __clz(lenL); if (kL > LEVELS - 1) kL = LEVELS - 1;
        float lm = fminf(s->tabmin[kL][lb], s->tabmin[kL][i - (1 << kL) + 1]);

        int lenR = rb - i + 1;
        int kR = 31 - __clz(lenR); if (kR > LEVELS - 1) kR = LEVELS - 1;
        float rm = fminf(s->tabmin[kR][i], s->tabmin[kR][rb - (1 << kR) + 1]);

        float prom = xi - fmaxf(lm, rm);
        bool peak  = (i > 0) && (i < N_PTS - 1) &&
                     (xi > s->xs[i - 1]) && (xi > s->xs[i + 1]);
        bool valid = peak && (prom >= PROM_MIN);
        promv[sgi]  = prom;
        validv[sgi] = valid;

        unsigned bal = __ballot_sync(0xffffffffu, valid);
        if (lane == 0) wcnt += __popc(bal);
    }
    if (lane == 0 && wcnt) atomicAdd(&s->cnt, wcnt);
    __syncthreads();

    bool useA = (s->cnt >= K);
    unsigned long long key[NE];
    #pragma unroll
    for (int sgi = 0; sgi < NE; sgi++) {
        int i = tid + NTHR * sgi;
        float sc = useA ? (validv[sgi] ? promv[sgi] : -INFINITY) : xv[sgi];
        key[sgi] = ((unsigned long long)ordf(sc) << 32) | (unsigned)(~(unsigned)i);
    }

    if (K <= 32) {
        // ---- phase 1: per-warp top-K via REDUX rounds (16 warps parallel) ----
        for (int it = 0; it < K; it++) {
            unsigned long long b = key[0];
            if (key[1] > b) b = key[1];
            unsigned long long win = warp_extract_max(b);
            if (lane == 0) s->wtop[w * K + it] = win;
            #pragma unroll
            for (int sgi = 0; sgi < NE; sgi++)
                if (key[sgi] == win) key[sgi] = 0ULL;
        }
        __syncthreads();

        // ---- phase 2: warp 0 selects global top-K from 16*K survivors ----
        if (w == 0) {
            unsigned long long pk[16];
            int total = NW * K;
            #pragma unroll
            for (int m = 0; m < 16; m++) {
                int idx = lane + 32 * m;
                pk[m] = (idx < total) ? s->wtop[idx] : 0ULL;
            }
            for (int it = 0; it < K; it++) {
                unsigned long long b = pk[0];
                #pragma unroll
                for (int m = 1; m < 16; m++)
                    if (pk[m] > b) b = pk[m];
                unsigned long long win = warp_extract_max(b);
                if (lane == 0) s->blk[it] = win;
                #pragma unroll
                for (int m = 0; m < 16; m++)
                    if (pk[m] == win) pk[m] = 0ULL;
            }
            int idx = (lane < K) ? (int)(~(unsigned)(s->blk[lane] & 0xffffffffULL))
                                 : 0x7fffffff;
            int rank = 0;
            #pragma unroll
            for (int m = 0; m < 32; m++) {
                int v = __shfl_sync(0xffffffffu, idx, m);
                rank += (v < idx) ? 1 : 0;
            }
            if (lane < K) out_idx_row[rank] = (float)idx;
        }
    } else {
        // generic cold path (K > 32)
        for (int it = tid; it < KMAX; it += NTHR) s->blk[it] = 0ULL;
        __syncthreads();
        for (int it = 0; it < K; it++) {
            unsigned long long b = key[0];
            if (key[1] > b) b = key[1];
            unsigned long long win = warp_extract_max(b);
            if (lane == 0) atomicMax(&s->blk[it], win);
            __syncthreads();
            unsigned widx = ~(unsigned)(s->blk[it] & 0xffffffffULL);
            #pragma unroll
            for (int sgi = 0; sgi < NE; sgi++)
                if ((unsigned)(tid + NTHR * sgi) == widx) key[sgi] = 0ULL;
        }
        if (tid == 0) {
            int sel[KMAX];
            for (int it = 0; it < K; it++)
                sel[it] = (int)(~(unsigned)(s->blk[it] & 0xffffffffULL));
            for (int a = 1; a < K; a++) {
                int v = sel[a], b = a - 1;
                while (b >= 0 && sel[b] > v) { sel[b + 1] = sel[b]; b--; }
                sel[b + 1] = v;
            }
            for (int a = 0; a < K; a++) out_idx_row[a] = (float)sel[a];
        }
    }
}

// ---------------------------------------------------------------------------
// Single fused kernel: 64 blocks x 512 threads, one row per block.
// ---------------------------------------------------------------------------
__global__ void __launch_bounds__(NTHR, 1)
fused_all(const float* __restrict__ tp,
          const float* __restrict__ W1, const float* __restrict__ b1,
          const float* __restrict__ W2, const float* __restrict__ b2,
          const float* __restrict__ W3, const float* __restrict__ b3,
          float* __restrict__ out_density,
          float* __restrict__ out_idx, int K)
{
    extern __shared__ char raw[];
    Shm* s = reinterpret_cast<Shm*>(raw);

    int row  = blockIdx.x;
    int tid  = threadIdx.x;
    int w    = tid >> 5;
    int lane = tid & 31;
    const float* x = tp + row * N_PTS;

    float tv[NE];
    float mn = INFINITY, mx = -INFINITY;
    #pragma unroll
    for (int sgi = 0; sgi < NE; sgi++) {
        float v = x[tid + NTHR * sgi];
        tv[sgi] = v;
        mn = fminf(mn, v);
        mx = fmaxf(mx, v);
    }
    if (tid < HID) s->w1r[tid] = fmaxf(W1[tid], 0.0f);
    if (tid == 0) s->nz = 0;

    #pragma unroll
    for (int o = 16; o; o >>= 1) {
        mn = fminf(mn, __shfl_xor_sync(0xffffffffu, mn, o));
        mx = fmaxf(mx, __shfl_xor_sync(0xffffffffu, mx, o));
    }
    if (lane == 0) { s->wmin[w] = mn; s->wmax[w] = mx; }
    if (tid < HID) {
        if (b1[tid] != 0.0f || b2[tid] != 0.0f) atomicAdd(&s->nz, 1);
    }
    __syncthreads();

    float tmin = s->wmin[0], tmaxv = s->wmax[0];
    #pragma unroll
    for (int i = 1; i < NW; i++) {
        tmin  = fminf(tmin,  s->wmin[i]);
        tmaxv = fmaxf(tmaxv, s->wmax[i]);
    }
    float inv = 1.0f / fmaxf(tmaxv - tmin, 1e-6f);

    // c-compute: 8 k-strips x 64 j-groups (float4)
    {
        int p  = tid >> 6;        // 0..7 : k strip of 32
        int jj = tid & 63;        // j group (4 consecutive j)
        const float4* W2v = reinterpret_cast<const float4*>(W2);
        float4 u4 = make_float4(0.f, 0.f, 0.f, 0.f);
        int k0 = p << 5;
        #pragma unroll 8
        for (int k = k0; k < k0 + 32; k++) {
            float wv = s->w1r[k];
            float4 r = W2v[k * (HID / 4) + jj];
            u4.x = fmaf(wv, r.x, u4.x);
            u4.y = fmaf(wv, r.y, u4.y);
            u4.z = fmaf(wv, r.z, u4.z);
            u4.w = fmaf(wv, r.w, u4.w);
        }
        reinterpret_cast<float4*>(s->part[p])[jj] = u4;
    }
    __syncthreads();
    {
        float rj = 0.0f;
        if (tid < HID) {
            float U = 0.0f;
            #pragma unroll
            for (int p = 0; p < 8; p++) U += s->part[p][tid];
            rj = fmaxf(U, 0.0f) * W3[tid];
        }
        #pragma unroll
        for (int o = 16; o; o >>= 1)
            rj += __shfl_xor_sync(0xffffffffu, rj, o);
        if (lane == 0) s->red[w] = rj;
    }
    __syncthreads();
    float c = 0.0f;
    #pragma unroll
    for (int i = 0; i < NW; i++) c += s->red[i];
    bool fast = (s->nz == 0);
    float b3v = b3[0];

    if (fast) {
        #pragma unroll
        for (int sgi = 0; sgi < NE; sgi++) {
            int i = tid + NTHR * sgi;
            float t = (tv[sgi] - tmin) * inv;
            float v = fmaf(c, t, b3v);
            float d = fmaxf(v, 0.0f) + log1pf(expf(-fabsf(v)));
            s->xs[i] = d;
            s->tabmax[0][i] = d;
            s->tabmin[0][i] = d;
            out_density[row * N_PTS + i] = d;
        }
    } else {
        #pragma unroll
        for (int sgi = 0; sgi < NE; sgi++) {
            int i = tid + NTHR * sgi;
            s->xs[i] = (tv[sgi] - tmin) * inv;
        }
        __syncthreads();
        for (int e = 0; e < N_PTS; e++) {
            float t = s->xs[e];
            if (tid < HID) s->h1[tid] = fmaxf(fmaf(t, W1[tid], b1[tid]), 0.0f);
            __syncthreads();
            float vj = 0.0f;
            if (tid < HID) {
                float acc = b2[tid];
                #pragma unroll 8
                for (int k = 0; k < HID; k++)
                    acc = fmaf(s->h1[k], W2[k * HID + tid], acc);
                vj = fmaxf(acc, 0.0f) * W3[tid];
            }
            #pragma unroll
            for (int o = 16; o; o >>= 1)
                vj += __shfl_xor_sync(0xffffffffu, vj, o);
            if (lane == 0) s->red[w] = vj;
            __syncthreads();
            if (tid == 0) {
                float sum = b3v;
                for (int i = 0; i < 8; i++) sum += s->red[i];   // warps 0..7 cover HID
                float d = fmaxf(sum, 0.0f) + log1pf(expf(-fabsf(sum)));
                out_density[row * N_PTS + e] = d;
                s->h1[0] = d;
            }
            __syncthreads();
            if (tid == 0) {
                float d = s->h1[0];
                s->xs[e] = d;
                s->tabmax[0][e] = d;
                s->tabmin[0][e] = d;
            }
            __syncthreads();
        }
    }
    __syncthreads();

    select_core(s, out_idx + row * K, K);
}

// ---------------------------------------------------------------------------
extern "C" void kernel_launch(void* const* d_in, const int* in_sizes, int n_in,
                              void* d_out, int out_size)
{
    const float* time_points = (const float*)d_in[0];
    const float* W1 = (const float*)d_in[2];
    const float* b1 = (const float*)d_in[3];
    const float* W2 = (const float*)d_in[4];
    const float* b2 = (const float*)d_in[5];
    const float* W3 = (const float*)d_in[6];
    const float* b3 = (const float*)d_in[7];

    float* out = (float*)d_out;
    float* out_density = out;
    float* out_indices = out + B_ROWS * N_PTS;

    int K = (out_size - B_ROWS * N_PTS) / B_ROWS;
    if (K < 1) K = 16;
    if (K > KMAX) K = KMAX;

    int smem = (int)sizeof(Shm);
    cudaFuncSetAttribute(fused_all, cudaFuncAttributeMaxDynamicSharedMemorySize, smem);

    fused_all<<<B_ROWS, NTHR, smem>>>(time_points, W1, b1, W2, b2, W3, b3,
                                      out_density, out_indices, K);
}

// round 11
// speedup vs baseline: 1.3383x; 1.1629x over previous
#include <cuda_runtime.h>
#include <math.h>

#define B_ROWS 64
#define N_PTS 1024
#define HID 256
#define KMAX 64
#define PROM_MIN 0.1f
#define LEVELS 10
#define NTHR 512
#define NE 2
#define NW 16

__device__ __forceinline__ unsigned ordf(float f) {
    unsigned u = __float_as_uint(f);
    return (u & 0x80000000u) ? ~u : (u | 0x80000000u);
}

struct alignas(16) Shm {
    float tabmax[LEVELS][N_PTS];   // level 0 = density values
    float tabmin[LEVELS][N_PTS];
    float score[N_PTS];            // prom scores (also tn scratch in fallback)
    int   plist[512];              // compacted peak indices (max 511 peaks)
    float part[8][HID];
    float w1r[HID];
    float red[NW];
    float wmin[NW], wmax[NW];
    unsigned long long wtop[NW * 32];
    unsigned long long blk[KMAX];
    int   cnt;
    int   pcount;
    int   nz;
    float h1[HID];
};

// one extraction round via 2 REDUX ops. key = (ordscore<<32) | ~index.
__device__ __forceinline__ unsigned long long warp_extract_max(unsigned long long b)
{
    unsigned bs   = (unsigned)(b >> 32);
    unsigned bidx = ~(unsigned)b;
    unsigned wmax = __reduce_max_sync(0xffffffffu, bs);
    unsigned cand = (bs == wmax) ? bidx : 0xffffffffu;
    unsigned widx = __reduce_min_sync(0xffffffffu, cand);
    return ((unsigned long long)wmax << 32) | (unsigned)(~widx);
}

// ---------------------------------------------------------------------------
// select core. Requires tabmax[0]/tabmin[0] filled with density, synced.
// ---------------------------------------------------------------------------
__device__ __forceinline__ void select_core(Shm* s, float* out_idx_row, int K)
{
    int tid  = threadIdx.x;
    int w    = tid >> 5;
    int lane = tid & 31;

    if (tid == 0) { s->cnt = 0; s->pcount = 0; }
    #pragma unroll
    for (int sgi = 0; sgi < NE; sgi++)
        s->score[tid + NTHR * sgi] = -INFINITY;

    // sparse table levels 1..9
    #pragma unroll
    for (int k = 1; k < LEVELS; k++) {
        int half = 1 << (k - 1);
        __syncthreads();
        #pragma unroll
        for (int sgi = 0; sgi < NE; sgi++) {
            int j  = tid + NTHR * sgi;
            int j2 = j + half; if (j2 > N_PTS - 1) j2 = N_PTS - 1;
            s->tabmax[k][j] = fmaxf(s->tabmax[k - 1][j], s->tabmax[k - 1][j2]);
            s->tabmin[k][j] = fminf(s->tabmin[k - 1][j], s->tabmin[k - 1][j2]);
        }
    }
    __syncthreads();

    // ---- peak detection + compaction ----
    #pragma unroll
    for (int sgi = 0; sgi < NE; sgi++) {
        int i = tid + NTHR * sgi;
        float xi = s->tabmax[0][i];
        bool peak = (i > 0) && (i < N_PTS - 1) &&
                    (xi > s->tabmax[0][i - 1]) && (xi > s->tabmax[0][i + 1]);
        unsigned bal = __ballot_sync(0xffffffffu, peak);
        int nb = __popc(bal);
        int base = 0;
        if (lane == 0 && nb) base = atomicAdd(&s->pcount, nb);
        base = __shfl_sync(0xffffffffu, base, 0);
        if (peak) {
            int rank = __popc(bal & ((1u << lane) - 1));
            s->plist[base + rank] = i;
        }
    }
    __syncthreads();

    // ---- prominence for compacted peaks only ----
    int np = s->pcount;
    int myvalid = 0;
    for (int p = tid; p < np; p += NTHR) {
        int i = s->plist[p];
        float xi = s->tabmax[0][i];

        int pos = i;
        #pragma unroll
        for (int k = LEVELS - 1; k >= 0; k--) {
            int cand = pos - (1 << k);
            if (cand >= 0 && s->tabmax[k][cand] <= xi) pos = cand;
        }
        int lb = pos - 1; if (lb < 0) lb = 0;

        int pos2 = i + 1;
        #pragma unroll
        for (int k = LEVELS - 1; k >= 0; k--) {
            if (pos2 + (1 << k) <= N_PTS && s->tabmax[k][pos2] <= xi) pos2 += (1 << k);
        }
        int rb = pos2; if (rb > N_PTS - 1) rb = N_PTS - 1;

        int lenL = i - lb + 1;
        int kL = 31 - __clz(lenL); if (kL > LEVELS - 1) kL = LEVELS - 1;
        float lm = fminf(s->tabmin[kL][lb], s->tabmin[kL][i - (1 << kL) + 1]);

        int lenR = rb - i + 1;
        int kR = 31 - __clz(lenR); if (kR > LEVELS - 1) kR = LEVELS - 1;
        float rm = fminf(s->tabmin[kR][i], s->tabmin[kR][rb - (1 << kR) + 1]);

        float prom = xi - fmaxf(lm, rm);
        s->score[i] = prom;
        if (prom >= PROM_MIN) myvalid++;
    }
    myvalid += __shfl_xor_sync(0xffffffffu, myvalid, 16);
    myvalid += __shfl_xor_sync(0xffffffffu, myvalid, 8);
    myvalid += __shfl_xor_sync(0xffffffffu, myvalid, 4);
    myvalid += __shfl_xor_sync(0xffffffffu, myvalid, 2);
    myvalid += __shfl_xor_sync(0xffffffffu, myvalid, 1);
    if (lane == 0 && myvalid) atomicAdd(&s->cnt, myvalid);
    __syncthreads();

    bool useA = (s->cnt >= K);
    unsigned long long key[NE];
    #pragma unroll
    for (int sgi = 0; sgi < NE; sgi++) {
        int i = tid + NTHR * sgi;
        float sc;
        if (useA) {
            float pr = s->score[i];
            sc = (pr >= PROM_MIN) ? pr : -INFINITY;
        } else {
            sc = s->tabmax[0][i];
        }
        key[sgi] = ((unsigned long long)ordf(sc) << 32) | (unsigned)(~(unsigned)i);
    }

    if (K <= 32) {
        // ---- phase 1: per-warp top-K via REDUX rounds ----
        for (int it = 0; it < K; it++) {
            unsigned long long b = key[0];
            if (key[1] > b) b = key[1];
            unsigned long long win = warp_extract_max(b);
            if (lane == 0) s->wtop[w * K + it] = win;
            #pragma unroll
            for (int sgi = 0; sgi < NE; sgi++)
                if (key[sgi] == win) key[sgi] = 0ULL;
        }
        __syncthreads();

        // ---- phase 2: warp 0 merges NW sorted lists via lane-held heads ----
        if (w == 0) {
            int ptr = 0;
            unsigned long long head = (lane < NW) ? s->wtop[lane * K] : 0ULL;
            int myidx = 0x7fffffff;
            for (int it = 0; it < K; it++) {
                unsigned long long win = warp_extract_max(head);
                if (lane < NW && head == win) {
                    ptr++;
                    head = (ptr < K) ? s->wtop[lane * K + ptr] : 0ULL;
                }
                if (lane == it) myidx = (int)(~(unsigned)(win & 0xffffffffULL));
            }
            // rank-sort K indices held one-per-lane
            int idx = (lane < K) ? myidx : 0x7fffffff;
            int rank = 0;
            #pragma unroll
            for (int m = 0; m < 32; m++) {
                int v = __shfl_sync(0xffffffffu, idx, m);
                rank += (v < idx) ? 1 : 0;
            }
            if (lane < K) out_idx_row[rank] = (float)idx;
        }
    } else {
        // generic cold path (K > 32)
        for (int it = tid; it < KMAX; it += NTHR) s->blk[it] = 0ULL;
        __syncthreads();
        for (int it = 0; it < K; it++) {
            unsigned long long b = key[0];
            if (key[1] > b) b = key[1];
            unsigned long long win = warp_extract_max(b);
            if (lane == 0) atomicMax(&s->blk[it], win);
            __syncthreads();
            unsigned widx = ~(unsigned)(s->blk[it] & 0xffffffffULL);
            #pragma unroll
            for (int sgi = 0; sgi < NE; sgi++)
                if ((unsigned)(tid + NTHR * sgi) == widx) key[sgi] = 0ULL;
        }
        if (tid == 0) {
            int sel[KMAX];
            for (int it = 0; it < K; it++)
                sel[it] = (int)(~(unsigned)(s->blk[it] & 0xffffffffULL));
            for (int a = 1; a < K; a++) {
                int v = sel[a], b = a - 1;
                while (b >= 0 && sel[b] > v) { sel[b + 1] = sel[b]; b--; }
                sel[b + 1] = v;
            }
            for (int a = 0; a < K; a++) out_idx_row[a] = (float)sel[a];
        }
    }
}

// ---------------------------------------------------------------------------
// Single fused kernel: 64 blocks x 512 threads, one row per block.
// ---------------------------------------------------------------------------
__global__ void __launch_bounds__(NTHR, 1)
fused_all(const float* __restrict__ tp,
          const float* __restrict__ W1, const float* __restrict__ b1,
          const float* __restrict__ W2, const float* __restrict__ b2,
          const float* __restrict__ W3, const float* __restrict__ b3,
          float* __restrict__ out_density,
          float* __restrict__ out_idx, int K)
{
    extern __shared__ char raw[];
    Shm* s = reinterpret_cast<Shm*>(raw);

    int row  = blockIdx.x;
    int tid  = threadIdx.x;
    int w    = tid >> 5;
    int lane = tid & 31;
    const float* x = tp + row * N_PTS;

    float tv[NE];
    float mn = INFINITY, mx = -INFINITY;
    #pragma unroll
    for (int sgi = 0; sgi < NE; sgi++) {
        float v = x[tid + NTHR * sgi];
        tv[sgi] = v;
        mn = fminf(mn, v);
        mx = fmaxf(mx, v);
    }
    if (tid < HID) s->w1r[tid] = fmaxf(W1[tid], 0.0f);
    if (tid == 0) s->nz = 0;

    #pragma unroll
    for (int o = 16; o; o >>= 1) {
        mn = fminf(mn, __shfl_xor_sync(0xffffffffu, mn, o));
        mx = fmaxf(mx, __shfl_xor_sync(0xffffffffu, mx, o));
    }
    if (lane == 0) { s->wmin[w] = mn; s->wmax[w] = mx; }
    if (tid < HID) {
        if (b1[tid] != 0.0f || b2[tid] != 0.0f) atomicAdd(&s->nz, 1);
    }
    __syncthreads();

    float tmin = s->wmin[0], tmaxv = s->wmax[0];
    #pragma unroll
    for (int i = 1; i < NW; i++) {
        tmin  = fminf(tmin,  s->wmin[i]);
        tmaxv = fmaxf(tmaxv, s->wmax[i]);
    }
    float inv = 1.0f / fmaxf(tmaxv - tmin, 1e-6f);

    // c-compute: 8 k-strips x 64 j-groups (float4)
    {
        int p  = tid >> 6;
        int jj = tid & 63;
        const float4* W2v = reinterpret_cast<const float4*>(W2);
        float4 u4 = make_float4(0.f, 0.f, 0.f, 0.f);
        int k0 = p << 5;
        #pragma unroll 8
        for (int k = k0; k < k0 + 32; k++) {
            float wv = s->w1r[k];
            float4 r = W2v[k * (HID / 4) + jj];
            u4.x = fmaf(wv, r.x, u4.x);
            u4.y = fmaf(wv, r.y, u4.y);
            u4.z = fmaf(wv, r.z, u4.z);
            u4.w = fmaf(wv, r.w, u4.w);
        }
        reinterpret_cast<float4*>(s->part[p])[jj] = u4;
    }
    __syncthreads();
    {
        float rj = 0.0f;
        if (tid < HID) {
            float U = 0.0f;
            #pragma unroll
            for (int p = 0; p < 8; p++) U += s->part[p][tid];
            rj = fmaxf(U, 0.0f) * W3[tid];
        }
        #pragma unroll
        for (int o = 16; o; o >>= 1)
            rj += __shfl_xor_sync(0xffffffffu, rj, o);
        if (lane == 0) s->red[w] = rj;
    }
    __syncthreads();
    float c = 0.0f;
    #pragma unroll
    for (int i = 0; i < NW; i++) c += s->red[i];
    bool fast = (s->nz == 0);
    float b3v = b3[0];

    if (fast) {
        #pragma unroll
        for (int sgi = 0; sgi < NE; sgi++) {
            int i = tid + NTHR * sgi;
            float t = (tv[sgi] - tmin) * inv;
            float v = fmaf(c, t, b3v);
            float d = fmaxf(v, 0.0f) + log1pf(expf(-fabsf(v)));
            s->tabmax[0][i] = d;
            s->tabmin[0][i] = d;
            out_density[row * N_PTS + i] = d;
        }
    } else {
        #pragma unroll
        for (int sgi = 0; sgi < NE; sgi++) {
            int i = tid + NTHR * sgi;
            s->score[i] = (tv[sgi] - tmin) * inv;   // tn scratch
        }
        __syncthreads();
        for (int e = 0; e < N_PTS; e++) {
            float t = s->score[e];
            if (tid < HID) s->h1[tid] = fmaxf(fmaf(t, W1[tid], b1[tid]), 0.0f);
            __syncthreads();
            float vj = 0.0f;
            if (tid < HID) {
                float acc = b2[tid];
                #pragma unroll 8
                for (int k = 0; k < HID; k++)
                    acc = fmaf(s->h1[k], W2[k * HID + tid], acc);
                vj = fmaxf(acc, 0.0f) * W3[tid];
            }
            #pragma unroll
            for (int o = 16; o; o >>= 1)
                vj += __shfl_xor_sync(0xffffffffu, vj, o);
            if (lane == 0) s->red[w] = vj;
            __syncthreads();
            if (tid == 0) {
                float sum = b3v;
                for (int i = 0; i < 8; i++) sum += s->red[i];
                float d = fmaxf(sum, 0.0f) + log1pf(expf(-fabsf(sum)));
                out_density[row * N_PTS + e] = d;
                s->tabmax[0][e] = d;
                s->tabmin[0][e] = d;
            }
            __syncthreads();
        }
    }
    __syncthreads();

    select_core(s, out_idx + row * K, K);
}

// ---------------------------------------------------------------------------
extern "C" void kernel_launch(void* const* d_in, const int* in_sizes, int n_in,
                              void* d_out, int out_size)
{
    const float* time_points = (const float*)d_in[0];
    const float* W1 = (const float*)d_in[2];
    const float* b1 = (const float*)d_in[3];
    const float* W2 = (const float*)d_in[4];
    const float* b2 = (const float*)d_in[5];
    const float* W3 = (const float*)d_in[6];
    const float* b3 = (const float*)d_in[7];

    float* out = (float*)d_out;
    float* out_density = out;
    float* out_indices = out + B_ROWS * N_PTS;

    int K = (out_size - B_ROWS * N_PTS) / B_ROWS;
    if (K < 1) K = 16;
    if (K > KMAX) K = KMAX;

    int smem = (int)sizeof(Shm);
    cudaFuncSetAttribute(fused_all, cudaFuncAttributeMaxDynamicSharedMemorySize, smem);

    fused_all<<<B_ROWS, NTHR, smem>>>(time_points, W1, b1, W2, b2, W3, b3,
                                      out_density, out_indices, K);
}